// round 1
// baseline (speedup 1.0000x reference)
#include <cuda_runtime.h>
#include <cstdint>

// ---------------- problem constants ----------------
#define BATCH 128
#define CH    256
#define TT    30
#define HH    16
#define WW    11
#define HW    176           // 16*11
#define NBINS 31
#define RED   16
#define KDIM  4096          // CH*RED
#define OUT   256
#define NCLS  10000
#define NB    (NBINS*BATCH) // 3968

// ---------------- scratch (static device, no malloc) ----------------
__device__ float g_p[(size_t)NBINS*BATCH*TT*CH];      // [n,b,t,c]  ~122MB
__device__ float g_pmax[NBINS*BATCH*CH];               // max over t
__device__ float g_pooled[(size_t)NBINS*BATCH*KDIM];   // [n,b,c*16+r]  ~65MB
__device__ float g_feat[NBINS*BATCH*CH];
__device__ float g_bn[NBINS*BATCH*OUT];
__device__ float g_invrn[NB];

// =====================================================================
// K1: horizontal strip pooling. Block = (b, t, 32-channel group).
// One pass over x: per-row (sum,max) over W, then combine rows for all
// 31 bins (p = 1,2,4,8,16). p[n,b,t,c] = strip_mean + strip_max.
// =====================================================================
__global__ __launch_bounds__(512) void k1_hmap(const float* __restrict__ x) {
    int bid = blockIdx.x;
    int cg = bid & 7;
    int t  = (bid >> 3) % TT;
    int b  = bid / (TT * 8);

    __shared__ float xs[32][180];      // 176 used
    __shared__ float rsum[32][16];
    __shared__ float rmax[32][16];

    const float* xb = x + (((size_t)b*CH + cg*32)*TT + t) * HW;
    int tid = threadIdx.x;

    // load 32 channels x 176 floats, float4 (44 per channel)
    for (int idx = tid; idx < 32*44; idx += 512) {
        int c = idx / 44, e = idx % 44;
        float4 v = *reinterpret_cast<const float4*>(xb + (size_t)c*TT*HW + e*4);
        *reinterpret_cast<float4*>(&xs[c][e*4]) = v;
    }
    __syncthreads();

    {   // per-row stats: thread = (channel, row)
        int c = tid >> 4, h = tid & 15;
        float s = 0.f, m = -1e30f;
        #pragma unroll
        for (int w = 0; w < WW; ++w) {
            float v = xs[c][h*WW + w];
            s += v; m = fmaxf(m, v);
        }
        rsum[c][h] = s; rmax[c][h] = m;
    }
    __syncthreads();

    // 31 bins x 32 channels
    for (int oi = tid; oi < NBINS*32; oi += 512) {
        int n = oi >> 5;
        int c = oi & 31;
        int start, len;
        if      (n == 0) { start = 0;          len = 16; }
        else if (n < 3)  { start = (n-1)*8;    len = 8;  }
        else if (n < 7)  { start = (n-3)*4;    len = 4;  }
        else if (n < 15) { start = (n-7)*2;    len = 2;  }
        else             { start = n-15;       len = 1;  }
        float s = 0.f, m = -1e30f;
        for (int h = 0; h < len; ++h) {
            s += rsum[c][start+h];
            m = fmaxf(m, rmax[c][start+h]);
        }
        float val = s / (float)(len*WW) + m;
        g_p[(((size_t)n*BATCH + b)*TT + t)*CH + cg*32 + c] = val;
    }
}

// =====================================================================
// K2: per (n,b): logits = p@Wmask, softmax over T, pooled = p^T@mask,
// plus pmax = max_t p (feeds the residual-max identity).
// =====================================================================
__global__ __launch_bounds__(256) void k2_mask(const float* __restrict__ Wmask) {
    int nb = blockIdx.x;
    int n = nb >> 7;
    int b = nb & 127;
    __shared__ float ps[TT][CH];       // 30720 B
    __shared__ float wms[CH][RED];     // 16384 B
    __shared__ float lg[TT][RED];      // 1920 B  (total 49024 <= 48KB)

    int tid = threadIdx.x;
    const float* pg = g_p + ((size_t)n*BATCH + b)*TT*CH;
    for (int i = tid; i < TT*CH/4; i += 256) {
        float4 v = *reinterpret_cast<const float4*>(pg + i*4);
        *reinterpret_cast<float4*>(&ps[0][0] + i*4) = v;
    }
    const float* wg = Wmask + (size_t)n*CH*RED;
    for (int i = tid; i < CH*RED/4; i += 256) {
        float4 v = *reinterpret_cast<const float4*>(wg + i*4);
        *reinterpret_cast<float4*>(&wms[0][0] + i*4) = v;
    }
    __syncthreads();

    // logits [30,16]
    for (int li = tid; li < TT*RED; li += 256) {
        int t = li >> 4, r = li & 15;
        float acc = 0.f;
        #pragma unroll 8
        for (int c = 0; c < CH; ++c) acc += ps[t][c] * wms[c][r];
        lg[t][r] = acc;
    }
    __syncthreads();

    // softmax over T per column r
    if (tid < RED) {
        int r = tid;
        float m = -1e30f;
        for (int t = 0; t < TT; ++t) m = fmaxf(m, lg[t][r]);
        float s = 0.f;
        for (int t = 0; t < TT; ++t) { float e = expf(lg[t][r] - m); lg[t][r] = e; s += e; }
        float inv = 1.f / s;
        for (int t = 0; t < TT; ++t) lg[t][r] *= inv;
    }
    __syncthreads();

    // pooled[c][r] + pmax[c]; thread = c
    {
        int c = tid;
        float acc[RED];
        #pragma unroll
        for (int r = 0; r < RED; ++r) acc[r] = 0.f;
        float pm = -1e30f;
        for (int t = 0; t < TT; ++t) {
            float pv = ps[t][c];
            pm = fmaxf(pm, pv);
            #pragma unroll
            for (int rq = 0; rq < 4; ++rq) {
                float4 mv = *reinterpret_cast<const float4*>(&lg[t][rq*4]);
                acc[rq*4+0] += pv*mv.x; acc[rq*4+1] += pv*mv.y;
                acc[rq*4+2] += pv*mv.z; acc[rq*4+3] += pv*mv.w;
            }
        }
        float* pd = g_pooled + ((size_t)n*BATCH + b)*KDIM + c*RED;
        #pragma unroll
        for (int r = 0; r < RED; r += 4)
            *reinterpret_cast<float4*>(pd + r) = make_float4(acc[r],acc[r+1],acc[r+2],acc[r+3]);
        g_pmax[((size_t)n*BATCH + b)*CH + c] = pm;
    }
}

// =====================================================================
// GEMM skeleton: BM=128, BN=64, BK=16, 256 threads, 8x4 regs,
// double-buffered smem, register-staged global prefetch.
// =====================================================================
// K3: out = leaky(pooled @ Wout);  feat = pmax + out
__global__ __launch_bounds__(256) void k3_wout(const float* __restrict__ Wout) {
    int n = blockIdx.y;
    int n0 = blockIdx.x * 64;
    const float* A = g_pooled + (size_t)n*BATCH*KDIM;   // [128,4096]
    const float* B = Wout + (size_t)n*KDIM*OUT;         // [4096,256]
    __shared__ float As[2][16][132];
    __shared__ float Bs[2][16][64];

    int tid = threadIdx.x;
    int tx = tid & 15, ty = tid >> 4;
    int am = tid >> 2, ak = (tid & 3) * 4;
    int bk = tid >> 4, bj = (tid & 15) * 4;

    float acc[8][4];
    #pragma unroll
    for (int i = 0; i < 8; ++i) {
        #pragma unroll
        for (int j = 0; j < 4; ++j) acc[i][j] = 0.f;
    }

    float4 rA0, rA1, rB;
    const int NT = KDIM / 16;

    rA0 = *reinterpret_cast<const float4*>(A + (size_t)am*KDIM + ak);
    rA1 = *reinterpret_cast<const float4*>(A + (size_t)(am+64)*KDIM + ak);
    rB  = *reinterpret_cast<const float4*>(B + (size_t)bk*OUT + n0 + bj);
    As[0][ak+0][am] = rA0.x; As[0][ak+1][am] = rA0.y; As[0][ak+2][am] = rA0.z; As[0][ak+3][am] = rA0.w;
    As[0][ak+0][am+64] = rA1.x; As[0][ak+1][am+64] = rA1.y; As[0][ak+2][am+64] = rA1.z; As[0][ak+3][am+64] = rA1.w;
    *reinterpret_cast<float4*>(&Bs[0][bk][bj]) = rB;
    __syncthreads();

    for (int t = 0; t < NT; ++t) {
        int cur = t & 1;
        if (t + 1 < NT) {
            int k0 = (t+1)*16;
            rA0 = *reinterpret_cast<const float4*>(A + (size_t)am*KDIM + k0 + ak);
            rA1 = *reinterpret_cast<const float4*>(A + (size_t)(am+64)*KDIM + k0 + ak);
            rB  = *reinterpret_cast<const float4*>(B + (size_t)(k0+bk)*OUT + n0 + bj);
        }
        #pragma unroll
        for (int kk = 0; kk < 16; ++kk) {
            float4 a0 = *reinterpret_cast<const float4*>(&As[cur][kk][ty*8]);
            float4 a1 = *reinterpret_cast<const float4*>(&As[cur][kk][ty*8+4]);
            float4 bv = *reinterpret_cast<const float4*>(&Bs[cur][kk][tx*4]);
            float av[8] = {a0.x,a0.y,a0.z,a0.w,a1.x,a1.y,a1.z,a1.w};
            float bb[4] = {bv.x,bv.y,bv.z,bv.w};
            #pragma unroll
            for (int i = 0; i < 8; ++i) {
                #pragma unroll
                for (int j = 0; j < 4; ++j) acc[i][j] += av[i]*bb[j];
            }
        }
        if (t + 1 < NT) {
            int nxt = 1 - cur;
            As[nxt][ak+0][am] = rA0.x; As[nxt][ak+1][am] = rA0.y; As[nxt][ak+2][am] = rA0.z; As[nxt][ak+3][am] = rA0.w;
            As[nxt][ak+0][am+64] = rA1.x; As[nxt][ak+1][am+64] = rA1.y; As[nxt][ak+2][am+64] = rA1.z; As[nxt][ak+3][am+64] = rA1.w;
            *reinterpret_cast<float4*>(&Bs[nxt][bk][bj]) = rB;
        }
        __syncthreads();
    }

    const float* pmx = g_pmax + (size_t)n*BATCH*CH;
    float* fp = g_feat + (size_t)n*BATCH*CH;
    #pragma unroll
    for (int i = 0; i < 8; ++i) {
        int m = ty*8 + i;
        float4 pm4 = *reinterpret_cast<const float4*>(pmx + m*CH + n0 + tx*4);
        float4 v;
        float o0 = acc[i][0], o1 = acc[i][1], o2 = acc[i][2], o3 = acc[i][3];
        v.x = (o0 >= 0.f ? o0 : 0.01f*o0) + pm4.x;
        v.y = (o1 >= 0.f ? o1 : 0.01f*o1) + pm4.y;
        v.z = (o2 >= 0.f ? o2 : 0.01f*o2) + pm4.z;
        v.w = (o3 >= 0.f ? o3 : 0.01f*o3) + pm4.w;
        *reinterpret_cast<float4*>(fp + m*CH + n0 + tx*4) = v;
    }
}

// K4: outputs = feat @ FForward -> d_out part 1 as [B, n, O]
__global__ __launch_bounds__(256) void k4_ff(const float* __restrict__ FF, float* __restrict__ out1) {
    int n = blockIdx.y;
    int n0 = blockIdx.x * 64;
    const float* A = g_feat + (size_t)n*BATCH*CH;    // [128,256]
    const float* B = FF + (size_t)n*CH*OUT;          // [256,256]
    __shared__ float As[2][16][132];
    __shared__ float Bs[2][16][64];

    int tid = threadIdx.x;
    int tx = tid & 15, ty = tid >> 4;
    int am = tid >> 2, ak = (tid & 3) * 4;
    int bk = tid >> 4, bj = (tid & 15) * 4;

    float acc[8][4];
    #pragma unroll
    for (int i = 0; i < 8; ++i) {
        #pragma unroll
        for (int j = 0; j < 4; ++j) acc[i][j] = 0.f;
    }
    float4 rA0, rA1, rB;
    const int NT = CH / 16;

    rA0 = *reinterpret_cast<const float4*>(A + am*CH + ak);
    rA1 = *reinterpret_cast<const float4*>(A + (am+64)*CH + ak);
    rB  = *reinterpret_cast<const float4*>(B + bk*OUT + n0 + bj);
    As[0][ak+0][am] = rA0.x; As[0][ak+1][am] = rA0.y; As[0][ak+2][am] = rA0.z; As[0][ak+3][am] = rA0.w;
    As[0][ak+0][am+64] = rA1.x; As[0][ak+1][am+64] = rA1.y; As[0][ak+2][am+64] = rA1.z; As[0][ak+3][am+64] = rA1.w;
    *reinterpret_cast<float4*>(&Bs[0][bk][bj]) = rB;
    __syncthreads();

    for (int t = 0; t < NT; ++t) {
        int cur = t & 1;
        if (t + 1 < NT) {
            int k0 = (t+1)*16;
            rA0 = *reinterpret_cast<const float4*>(A + am*CH + k0 + ak);
            rA1 = *reinterpret_cast<const float4*>(A + (am+64)*CH + k0 + ak);
            rB  = *reinterpret_cast<const float4*>(B + (k0+bk)*OUT + n0 + bj);
        }
        #pragma unroll
        for (int kk = 0; kk < 16; ++kk) {
            float4 a0 = *reinterpret_cast<const float4*>(&As[cur][kk][ty*8]);
            float4 a1 = *reinterpret_cast<const float4*>(&As[cur][kk][ty*8+4]);
            float4 bv = *reinterpret_cast<const float4*>(&Bs[cur][kk][tx*4]);
            float av[8] = {a0.x,a0.y,a0.z,a0.w,a1.x,a1.y,a1.z,a1.w};
            float bb[4] = {bv.x,bv.y,bv.z,bv.w};
            #pragma unroll
            for (int i = 0; i < 8; ++i) {
                #pragma unroll
                for (int j = 0; j < 4; ++j) acc[i][j] += av[i]*bb[j];
            }
        }
        if (t + 1 < NT) {
            int nxt = 1 - cur;
            As[nxt][ak+0][am] = rA0.x; As[nxt][ak+1][am] = rA0.y; As[nxt][ak+2][am] = rA0.z; As[nxt][ak+3][am] = rA0.w;
            As[nxt][ak+0][am+64] = rA1.x; As[nxt][ak+1][am+64] = rA1.y; As[nxt][ak+2][am+64] = rA1.z; As[nxt][ak+3][am+64] = rA1.w;
            *reinterpret_cast<float4*>(&Bs[nxt][bk][bj]) = rB;
        }
        __syncthreads();
    }

    #pragma unroll
    for (int i = 0; i < 8; ++i) {
        int m = ty*8 + i;
        *reinterpret_cast<float4*>(out1 + (size_t)m*(NBINS*OUT) + n*OUT + n0 + tx*4) =
            make_float4(acc[i][0], acc[i][1], acc[i][2], acc[i][3]);
    }
}

// K5: per-bin BatchNorm (training stats over B), two-pass for accuracy.
__global__ __launch_bounds__(256) void k5_bn(const float* __restrict__ out1,
                                             const float* __restrict__ gamma,
                                             const float* __restrict__ beta) {
    int n = blockIdx.x, o = threadIdx.x;
    const float* base = out1 + n*OUT + o;      // stride NBINS*OUT per b
    const int STR = NBINS*OUT;
    float s = 0.f;
    for (int b = 0; b < BATCH; ++b) s += base[(size_t)b*STR];
    float mean = s * (1.f/BATCH);
    float v = 0.f;
    for (int b = 0; b < BATCH; ++b) { float d = base[(size_t)b*STR] - mean; v += d*d; }
    v *= (1.f/BATCH);
    float istd = rsqrtf(v + 1e-5f);
    float g = gamma[n*OUT + o], be = beta[n*OUT + o];
    float* bnp = g_bn + (size_t)n*BATCH*OUT + o;
    for (int b = 0; b < BATCH; ++b)
        bnp[(size_t)b*OUT] = g * (base[(size_t)b*STR] - mean) * istd + be;
}

// K5b: inverse row L2 norms of bn
__global__ __launch_bounds__(64) void k5b_rn() {
    int nb = blockIdx.x;
    int tid = threadIdx.x;
    const float* r = g_bn + (size_t)nb*OUT;
    float s = 0.f;
    for (int i = tid; i < OUT; i += 64) { float v = r[i]; s += v*v; }
    #pragma unroll
    for (int o = 16; o > 0; o >>= 1) s += __shfl_xor_sync(0xffffffffu, s, o);
    __shared__ float ws[2];
    if ((tid & 31) == 0) ws[tid >> 5] = s;
    __syncthreads();
    if (tid == 0) g_invrn[nb] = 1.f / fmaxf(sqrtf(ws[0] + ws[1]), 1e-12f);
}

// K6: logits = (bn @ fc1d) * invrow * invcol;  colnorm^2 accumulated
// from the smem B tiles inside the K loop (no extra fc1d pass).
__global__ __launch_bounds__(256) void k6_logits(const float* __restrict__ fc,
                                                 float* __restrict__ out2) {
    int n = blockIdx.y;
    int n0 = blockIdx.x * 64;
    const float* A = g_bn + (size_t)n*BATCH*OUT;        // [128,256]
    const float* B = fc + (size_t)n*OUT*NCLS;           // [256,10000]
    __shared__ float As[2][16][132];
    __shared__ float Bs[2][16][64];
    __shared__ float csq[4][64];

    int tid = threadIdx.x;
    int tx = tid & 15, ty = tid >> 4;
    int am = tid >> 2, ak = (tid & 3) * 4;
    int bk = tid >> 4, bj = (tid & 15) * 4;
    int cq = tid & 63, kq = tid >> 6;

    float acc[8][4];
    #pragma unroll
    for (int i = 0; i < 8; ++i) {
        #pragma unroll
        for (int j = 0; j < 4; ++j) acc[i][j] = 0.f;
    }
    float bsq = 0.f;
    float4 rA0, rA1, rB;
    const int NT = OUT / 16;
    bool bvalid = (n0 + bj + 3) < NCLS;   // whole float4 valid or invalid (4 | 10000)

    rA0 = *reinterpret_cast<const float4*>(A + am*OUT + ak);
    rA1 = *reinterpret_cast<const float4*>(A + (am+64)*OUT + ak);
    rB  = bvalid ? *reinterpret_cast<const float4*>(B + (size_t)bk*NCLS + n0 + bj)
                 : make_float4(0.f,0.f,0.f,0.f);
    As[0][ak+0][am] = rA0.x; As[0][ak+1][am] = rA0.y; As[0][ak+2][am] = rA0.z; As[0][ak+3][am] = rA0.w;
    As[0][ak+0][am+64] = rA1.x; As[0][ak+1][am+64] = rA1.y; As[0][ak+2][am+64] = rA1.z; As[0][ak+3][am+64] = rA1.w;
    *reinterpret_cast<float4*>(&Bs[0][bk][bj]) = rB;
    __syncthreads();

    for (int t = 0; t < NT; ++t) {
        int cur = t & 1;
        if (t + 1 < NT) {
            int k0 = (t+1)*16;
            rA0 = *reinterpret_cast<const float4*>(A + am*OUT + k0 + ak);
            rA1 = *reinterpret_cast<const float4*>(A + (am+64)*OUT + k0 + ak);
            rB  = bvalid ? *reinterpret_cast<const float4*>(B + (size_t)(k0+bk)*NCLS + n0 + bj)
                         : make_float4(0.f,0.f,0.f,0.f);
        }
        #pragma unroll
        for (int kk = 0; kk < 16; ++kk) {
            float4 a0 = *reinterpret_cast<const float4*>(&As[cur][kk][ty*8]);
            float4 a1 = *reinterpret_cast<const float4*>(&As[cur][kk][ty*8+4]);
            float4 bv = *reinterpret_cast<const float4*>(&Bs[cur][kk][tx*4]);
            float av[8] = {a0.x,a0.y,a0.z,a0.w,a1.x,a1.y,a1.z,a1.w};
            float bb[4] = {bv.x,bv.y,bv.z,bv.w};
            #pragma unroll
            for (int i = 0; i < 8; ++i) {
                #pragma unroll
                for (int j = 0; j < 4; ++j) acc[i][j] += av[i]*bb[j];
            }
        }
        // column sum-of-squares from this tile (reads cur; overwrite is next iter, post-sync)
        #pragma unroll
        for (int kk2 = 0; kk2 < 4; ++kk2) { float v = Bs[cur][kq*4 + kk2][cq]; bsq += v*v; }
        if (t + 1 < NT) {
            int nxt = 1 - cur;
            As[nxt][ak+0][am] = rA0.x; As[nxt][ak+1][am] = rA0.y; As[nxt][ak+2][am] = rA0.z; As[nxt][ak+3][am] = rA0.w;
            As[nxt][ak+0][am+64] = rA1.x; As[nxt][ak+1][am+64] = rA1.y; As[nxt][ak+2][am+64] = rA1.z; As[nxt][ak+3][am+64] = rA1.w;
            *reinterpret_cast<float4*>(&Bs[nxt][bk][bj]) = rB;
        }
        __syncthreads();
    }

    csq[kq][cq] = bsq;
    __syncthreads();

    float invc[4];
    #pragma unroll
    for (int j = 0; j < 4; ++j) {
        int c = tx*4 + j;
        float ss = csq[0][c] + csq[1][c] + csq[2][c] + csq[3][c];
        invc[j] = 1.f / fmaxf(sqrtf(ss), 1e-12f);
    }
    if ((n0 + tx*4 + 3) < NCLS) {
        #pragma unroll
        for (int i = 0; i < 8; ++i) {
            int m = ty*8 + i;
            float ir = g_invrn[n*BATCH + m];
            float4 v = make_float4(acc[i][0]*ir*invc[0], acc[i][1]*ir*invc[1],
                                   acc[i][2]*ir*invc[2], acc[i][3]*ir*invc[3]);
            *reinterpret_cast<float4*>(out2 + (size_t)m*(NBINS*NCLS) + n*NCLS + n0 + tx*4) = v;
        }
    }
}

// =====================================================================
extern "C" void kernel_launch(void* const* d_in, const int* in_sizes, int n_in,
                              void* d_out, int out_size) {
    const float* x     = (const float*)d_in[0];
    const float* Wmask = (const float*)d_in[1];
    const float* Wout  = (const float*)d_in[2];
    const float* FF    = (const float*)d_in[3];
    const float* gamma = (const float*)d_in[4];
    const float* beta  = (const float*)d_in[5];
    const float* fc1d  = (const float*)d_in[6];
    float* out  = (float*)d_out;
    float* out1 = out;                                   // [128,31,256]
    float* out2 = out + (size_t)BATCH*NBINS*OUT;         // [128,31,10000]

    k1_hmap<<<BATCH*TT*8, 512>>>(x);
    k2_mask<<<NB, 256>>>(Wmask);
    k3_wout<<<dim3(4, NBINS), 256>>>(Wout);
    k4_ff<<<dim3(4, NBINS), 256>>>(FF, out1);
    k5_bn<<<NBINS, 256>>>(out1, gamma, beta);
    k5b_rn<<<NB, 64>>>();
    k6_logits<<<dim3((NCLS + 63) / 64, NBINS), 256>>>(fc1d, out2);
}